// round 15
// baseline (speedup 1.0000x reference)
#include <cuda_runtime.h>
#include <cuda_fp16.h>
#include <cstdint>

// Problem constants
#define Bdim   8
#define Ndim   2048
#define Kdim   32
#define Fin    256
#define C2     512            // 2*F_OUT
#define MROWS  (Bdim * Ndim)  // 16384

// GEMM tile config (tf32 mma.sync path)
#define BM   128
#define BN   128
#define BK   16
#define BMP  132              // padded smem row stride (floats)

#define STAT_BLOCKS 128
#define GATHER_BLOCKS 148     // one persistent gather CTA per SM in wave 1

// --------- scratch (device globals: allocation-guard safe) ----------
__device__ __half g_xhalf[MROWS * Fin];               // 8.4 MB fp16 mirror of x
__device__ float  g_xneib[MROWS * Fin];               // 16.8 MB
__device__ float  g_partS[C2 * STAT_BLOCKS];          // transposed: [c][block]
__device__ float  g_partQ[C2 * STAT_BLOCKS];
__device__ float  g_scale[C2];
__device__ float  g_shift[C2];

// ====================================================================
// tf32 helpers (Ampere-class mma.sync — the only tensor path the
// harness's sm_103 PTX target accepts; tcgen05 is rejected at ptxas)
// ====================================================================
__device__ __forceinline__ float to_tf32(float x) {
    float r;
    asm("cvt.rna.tf32.f32 %0, %1;" : "=f"(r) : "f"(x));
    return r;
}

__device__ __forceinline__ void mma_tf32(float* c, const uint32_t* a, const uint32_t* b) {
    asm volatile(
        "mma.sync.aligned.m16n8k8.row.col.f32.tf32.tf32.f32 "
        "{%0,%1,%2,%3}, {%4,%5,%6,%7}, {%8,%9}, {%0,%1,%2,%3};"
        : "+f"(c[0]), "+f"(c[1]), "+f"(c[2]), "+f"(c[3])
        : "r"(a[0]), "r"(a[1]), "r"(a[2]), "r"(a[3]),
          "r"(b[0]), "r"(b[1]));
}

struct SmemGemm {
    float As[2][BK][BMP];
    float Ws[2][BK][BMP];
};

// ====================================================================
// Kernel 0: fp32 -> fp16 mirror of x. Each thread converts 8 floats.
// ====================================================================
__global__ void __launch_bounds__(256)
convert_half_kernel(const float* __restrict__ x)
{
    const int i = blockIdx.x * 256 + threadIdx.x;     // 8 floats per thread
    const float4 a = ((const float4*)x)[2 * i];
    const float4 b = ((const float4*)x)[2 * i + 1];
    __half2 h[4];
    h[0] = __floats2half2_rn(a.x, a.y);
    h[1] = __floats2half2_rn(a.z, a.w);
    h[2] = __floats2half2_rn(b.x, b.y);
    h[3] = __floats2half2_rn(b.z, b.w);
    ((uint4*)g_xhalf)[i] = *(const uint4*)h;
}

// ====================================================================
// GEMM tile worker (proven R5/R14): 128x128 tile of
//   H[rowBase.., outColBase..] = A[rowBase..,:] @ W[colBase..,:]^T + bias
// 256 threads, 8 warps (4x2) each 32x64, BK=16 double-buffered.
// ====================================================================
__device__ __forceinline__ void gemm_tile(
    const float* __restrict__ A, const float* __restrict__ W,
    const float* __restrict__ bias,
    int rowBase, int colBase, int outColBase,
    float* __restrict__ H, SmemGemm* sm)
{
    const int tid  = threadIdx.x;
    const int lane = tid & 31;
    const int warp = tid >> 5;
    const int wm = (warp & 3) * 32;
    const int wn = (warp >> 2) * 64;
    const int g  = lane >> 2;
    const int t  = lane & 3;

    float acc[2][8][4];
#pragma unroll
    for (int mt = 0; mt < 2; mt++)
#pragma unroll
        for (int nt = 0; nt < 8; nt++)
#pragma unroll
            for (int i = 0; i < 4; i++) acc[mt][nt][i] = 0.f;

    const int srow = tid >> 2;
    const int skq  = tid & 3;

#define STAGE(buf, k0)                                                          \
    {                                                                           \
        _Pragma("unroll")                                                       \
        for (int tt = 0; tt < 2; tt++) {                                        \
            const int row = srow + 64 * tt;                                     \
            float4 va = *(const float4*)(A + (size_t)(rowBase + row) * Fin + (k0) + skq * 4); \
            sm->As[buf][skq * 4 + 0][row] = to_tf32(va.x);                      \
            sm->As[buf][skq * 4 + 1][row] = to_tf32(va.y);                      \
            sm->As[buf][skq * 4 + 2][row] = to_tf32(va.z);                      \
            sm->As[buf][skq * 4 + 3][row] = to_tf32(va.w);                      \
            float4 vw = *(const float4*)(W + (size_t)(colBase + row) * Fin + (k0) + skq * 4); \
            sm->Ws[buf][skq * 4 + 0][row] = to_tf32(vw.x);                      \
            sm->Ws[buf][skq * 4 + 1][row] = to_tf32(vw.y);                      \
            sm->Ws[buf][skq * 4 + 2][row] = to_tf32(vw.z);                      \
            sm->Ws[buf][skq * 4 + 3][row] = to_tf32(vw.w);                      \
        }                                                                       \
    }

    STAGE(0, 0);
    __syncthreads();

    const int NSTAGE = Fin / BK;  // 16
    for (int s = 0; s < NSTAGE; s++) {
        if (s + 1 < NSTAGE) STAGE((s + 1) & 1, (s + 1) * BK);
        const int buf = s & 1;

#pragma unroll
        for (int ks = 0; ks < 2; ks++) {
            const int k8 = ks * 8;
            uint32_t a[2][4];
#pragma unroll
            for (int mt = 0; mt < 2; mt++) {
                const int m0 = wm + mt * 16 + g;
                a[mt][0] = __float_as_uint(sm->As[buf][k8 + t][m0]);
                a[mt][1] = __float_as_uint(sm->As[buf][k8 + t][m0 + 8]);
                a[mt][2] = __float_as_uint(sm->As[buf][k8 + t + 4][m0]);
                a[mt][3] = __float_as_uint(sm->As[buf][k8 + t + 4][m0 + 8]);
            }
            uint32_t b[8][2];
#pragma unroll
            for (int nt = 0; nt < 8; nt++) {
                const int n0 = wn + nt * 8 + g;
                b[nt][0] = __float_as_uint(sm->Ws[buf][k8 + t][n0]);
                b[nt][1] = __float_as_uint(sm->Ws[buf][k8 + t + 4][n0]);
            }
#pragma unroll
            for (int mt = 0; mt < 2; mt++)
#pragma unroll
                for (int nt = 0; nt < 8; nt++)
                    mma_tf32(acc[mt][nt], a[mt], b[nt]);
        }
        __syncthreads();
    }
#undef STAGE

#pragma unroll
    for (int nt = 0; nt < 8; nt++) {
        const int c = wn + nt * 8 + t * 2;
        const float b0 = bias[colBase + c];
        const float b1 = bias[colBase + c + 1];
#pragma unroll
        for (int mt = 0; mt < 2; mt++) {
            const int r0 = rowBase + wm + mt * 16 + g;
            float2 v0 = make_float2(acc[mt][nt][0] + b0, acc[mt][nt][1] + b1);
            float2 v1 = make_float2(acc[mt][nt][2] + b0, acc[mt][nt][3] + b1);
            *(float2*)(H + (size_t)r0 * C2 + outColBase + c)       = v0;
            *(float2*)(H + (size_t)(r0 + 8) * C2 + outColBase + c) = v1;
        }
    }
}

// ====================================================================
// Phase 1: block-specialized launch.
//   blocks [0, 148):    PERSISTENT fp16 gather-mean -> g_xneib (fp32)
//                       (wave-1 places one per SM; resident all phase)
//   blocks [148, 404):  self GEMM   H[:, 0:256] = X @ Wx^T + Wx_b
// Gather is warp-autonomous: idx broadcast via shfl, no smem, no bar.
// ====================================================================
__global__ void __launch_bounds__(256, 2)
phase1_kernel(const float* __restrict__ x, const int* __restrict__ idx,
              const float* __restrict__ Wx, const float* __restrict__ Wxb,
              float* __restrict__ H)
{
    __shared__ SmemGemm sh;

    if (blockIdx.x >= GATHER_BLOCKS) {
        const int tileId  = blockIdx.x - GATHER_BLOCKS;
        const int rowBase = (tileId >> 1) * BM;
        const int colBase = (tileId & 1) * BN;
        gemm_tile(x, Wx, Wxb, rowBase, colBase, colBase, H, &sh);
        return;
    }

    // ---- persistent gather: warp w owns batch w; lane owns one uint4 (8 halves)
    const int w    = threadIdx.x >> 5;     // batch 0..7
    const int lane = threadIdx.x & 31;     // uint4 lane within 512B fp16 row
    const uint4* __restrict__ Xh = (const uint4*)g_xhalf;   // row = 32 uint4
    const float s = 1.0f / (float)Kdim;

    for (int n = blockIdx.x; n < Ndim; n += GATHER_BLOCKS) {
        const int myidx = idx[n * Kdim + lane];
        float acc[8];
#pragma unroll
        for (int i = 0; i < 8; i++) acc[i] = 0.f;

#pragma unroll
        for (int k = 0; k < Kdim; k++) {
            const int j = __shfl_sync(0xffffffffu, myidx, k);
            uint4 v = Xh[(size_t)(((w << 11) + j) << 5) + lane];
            const __half2* h = (const __half2*)&v;
#pragma unroll
            for (int p = 0; p < 4; p++) {
                float2 f = __half22float2(h[p]);
                acc[2 * p]     += f.x;
                acc[2 * p + 1] += f.y;
            }
        }
        float4 o0 = make_float4(acc[0] * s, acc[1] * s, acc[2] * s, acc[3] * s);
        float4 o1 = make_float4(acc[4] * s, acc[5] * s, acc[6] * s, acc[7] * s);
        float* dst = g_xneib + (size_t)(((w << 11) + n) << 8) + lane * 8;
        *(float4*)(dst)     = o0;
        *(float4*)(dst + 4) = o1;
    }
}

// ====================================================================
// Phase 2: neighbor GEMM  H[:, 256:512] = xneib @ Wn^T + Wn_b
// ====================================================================
__global__ void __launch_bounds__(256, 2)
gemm_neib_kernel(const float* __restrict__ Wn, const float* __restrict__ Wnb,
                 float* __restrict__ H)
{
    __shared__ SmemGemm sh;
    const int rowBase = blockIdx.x * BM;
    const int colBase = blockIdx.y * BN;
    gemm_tile(g_xneib, Wn, Wnb, rowBase, colBase, 256 + colBase, H, &sh);
}

// ====================================================================
// Kernel 3: per-row L2 normalize + ReLU (in place), per-channel partials.
// ====================================================================
__global__ void __launch_bounds__(256)
norm_relu_stats_kernel(float* __restrict__ H)
{
    const int wid    = threadIdx.x >> 5;
    const int lane   = threadIdx.x & 31;
    const int gwarp  = blockIdx.x * 8 + wid;
    const int nwarps = gridDim.x * 8;

    float s[16], q[16];
#pragma unroll
    for (int i = 0; i < 16; i++) { s[i] = 0.f; q[i] = 0.f; }

    for (int r = gwarp; r < MROWS; r += nwarps) {
        float4* __restrict__ Hr = (float4*)(H + (size_t)r * C2);
        float4 v[4];
#pragma unroll
        for (int j = 0; j < 4; j++) v[j] = Hr[j * 32 + lane];

        float ss = 0.f;
#pragma unroll
        for (int j = 0; j < 4; j++)
            ss += v[j].x * v[j].x + v[j].y * v[j].y + v[j].z * v[j].z + v[j].w * v[j].w;
#pragma unroll
        for (int o = 16; o > 0; o >>= 1)
            ss += __shfl_xor_sync(0xffffffffu, ss, o);

        const float inv = 1.0f / fmaxf(sqrtf(ss), 1e-12f);
#pragma unroll
        for (int j = 0; j < 4; j++) {
            float4 u;
            u.x = fmaxf(v[j].x * inv, 0.f);
            u.y = fmaxf(v[j].y * inv, 0.f);
            u.z = fmaxf(v[j].z * inv, 0.f);
            u.w = fmaxf(v[j].w * inv, 0.f);
            Hr[j * 32 + lane] = u;
            s[j * 4 + 0] += u.x;  q[j * 4 + 0] += u.x * u.x;
            s[j * 4 + 1] += u.y;  q[j * 4 + 1] += u.y * u.y;
            s[j * 4 + 2] += u.z;  q[j * 4 + 2] += u.z * u.z;
            s[j * 4 + 3] += u.w;  q[j * 4 + 3] += u.w * u.w;
        }
    }

    __shared__ float smS[8][C2];
    __shared__ float smQ[8][C2];
#pragma unroll
    for (int j = 0; j < 4; j++)
#pragma unroll
        for (int i = 0; i < 4; i++) {
            const int c = j * 128 + lane * 4 + i;
            smS[wid][c] = s[j * 4 + i];
            smQ[wid][c] = q[j * 4 + i];
        }
    __syncthreads();

    for (int c = threadIdx.x; c < C2; c += blockDim.x) {
        float S = 0.f, Q = 0.f;
#pragma unroll
        for (int w = 0; w < 8; w++) { S += smS[w][c]; Q += smQ[w][c]; }
        g_partS[c * STAT_BLOCKS + blockIdx.x] = S;
        g_partQ[c * STAT_BLOCKS + blockIdx.x] = Q;
    }
}

// ====================================================================
// Kernel 4: finalize BN stats. 64 blocks x 8 warps = one warp per channel;
// coalesced float4 reads of the transposed partials.
// ====================================================================
__global__ void __launch_bounds__(256)
bn_finalize_kernel(const float* __restrict__ gamma, const float* __restrict__ beta)
{
    const int c    = blockIdx.x * 8 + (threadIdx.x >> 5);   // 0..511
    const int lane = threadIdx.x & 31;
    float4 s4 = *(const float4*)&g_partS[c * STAT_BLOCKS + lane * 4];
    float4 q4 = *(const float4*)&g_partQ[c * STAT_BLOCKS + lane * 4];
    float S = s4.x + s4.y + s4.z + s4.w;
    float Q = q4.x + q4.y + q4.z + q4.w;
#pragma unroll
    for (int o = 16; o > 0; o >>= 1) {
        S += __shfl_xor_sync(0xffffffffu, S, o);
        Q += __shfl_xor_sync(0xffffffffu, Q, o);
    }
    if (lane == 0) {
        const float invN = 1.0f / (float)MROWS;
        const float mean = S * invN;
        const float var  = Q * invN - mean * mean;
        const float sc   = gamma[c] * rsqrtf(var + 1e-5f);
        g_scale[c] = sc;
        g_shift[c] = beta[c] - mean * sc;
    }
}

// ====================================================================
// Kernel 5: apply BN in place:  y = u*scale[c] + shift[c]
// ====================================================================
__global__ void __launch_bounds__(256)
bn_apply_kernel(float* __restrict__ H)
{
    __shared__ float4 ssc[C2 / 4];
    __shared__ float4 ssh[C2 / 4];
    for (int i = threadIdx.x; i < C2 / 4; i += blockDim.x) {
        ssc[i] = ((const float4*)g_scale)[i];
        ssh[i] = ((const float4*)g_shift)[i];
    }
    __syncthreads();

    const int total = MROWS * C2 / 4;
    float4* __restrict__ H4 = (float4*)H;
    for (int idx = blockIdx.x * blockDim.x + threadIdx.x; idx < total;
         idx += gridDim.x * blockDim.x) {
        const int c4 = idx & (C2 / 4 - 1);
        float4 v = H4[idx];
        const float4 sc = ssc[c4];
        const float4 sh = ssh[c4];
        v.x = v.x * sc.x + sh.x;
        v.y = v.y * sc.y + sh.y;
        v.z = v.z * sc.z + sh.z;
        v.w = v.w * sc.w + sh.w;
        H4[idx] = v;
    }
}

// ====================================================================
// Launch
// ====================================================================
extern "C" void kernel_launch(void* const* d_in, const int* in_sizes, int n_in,
                              void* d_out, int out_size)
{
    const float* x     = (const float*)d_in[0];
    const int*   idx   = (const int*)  d_in[1];
    const float* Wxw   = (const float*)d_in[2];
    const float* Wxb   = (const float*)d_in[3];
    const float* Wnw   = (const float*)d_in[4];
    const float* Wnb   = (const float*)d_in[5];
    const float* gamma = (const float*)d_in[6];
    const float* beta  = (const float*)d_in[7];
    float* H = (float*)d_out;

    // fp16 mirror of x (feeds the gather only; GEMM numerics unchanged)
    convert_half_kernel<<<MROWS * Fin / 8 / 256, 256>>>(x);

    // Phase 1: 148 persistent gather blocks (one per SM) + 256 self-GEMM tiles
    phase1_kernel<<<GATHER_BLOCKS + 256, 256>>>(x, idx, Wxw, Wxb, H);

    // Phase 2: neighbor GEMM
    dim3 ngrid(MROWS / BM, 2);
    gemm_neib_kernel<<<ngrid, 256>>>(Wnw, Wnb, H);

    norm_relu_stats_kernel<<<STAT_BLOCKS, 256>>>(H);
    bn_finalize_kernel<<<64, 256>>>(gamma, beta);
    bn_apply_kernel<<<4096, 256>>>(H);
}

// round 16
// speedup vs baseline: 1.0952x; 1.0952x over previous
#include <cuda_runtime.h>
#include <cuda_fp16.h>
#include <cstdint>

// Problem constants
#define Bdim   8
#define Ndim   2048
#define Kdim   32
#define Fin    256
#define C2     512            // 2*F_OUT
#define MROWS  (Bdim * Ndim)  // 16384

// GEMM tile config (tf32 mma.sync path)
#define BM   128
#define BN   128
#define BK   16
#define BMP  132              // padded smem row stride (floats)

#define STAT_BLOCKS 592       // 4 blocks/SM on 148 SMs

// --------- scratch (device globals: allocation-guard safe) ----------
__device__ __half g_xhalf[MROWS * Fin];               // 8.4 MB fp16 mirror of x
__device__ float  g_xneib[MROWS * Fin];               // 16.8 MB
__device__ float  g_inv[MROWS];                       // per-row 1/max(||h||,eps)
__device__ float  g_partS[C2 * STAT_BLOCKS];          // transposed: [c][block]
__device__ float  g_partQ[C2 * STAT_BLOCKS];
__device__ float  g_scale[C2];
__device__ float  g_shift[C2];

// ====================================================================
// tf32 helpers (Ampere-class mma.sync — the only tensor path the
// harness's sm_103 PTX target accepts; tcgen05 is rejected at ptxas)
// ====================================================================
__device__ __forceinline__ float to_tf32(float x) {
    float r;
    asm("cvt.rna.tf32.f32 %0, %1;" : "=f"(r) : "f"(x));
    return r;
}

__device__ __forceinline__ void mma_tf32(float* c, const uint32_t* a, const uint32_t* b) {
    asm volatile(
        "mma.sync.aligned.m16n8k8.row.col.f32.tf32.tf32.f32 "
        "{%0,%1,%2,%3}, {%4,%5,%6,%7}, {%8,%9}, {%0,%1,%2,%3};"
        : "+f"(c[0]), "+f"(c[1]), "+f"(c[2]), "+f"(c[3])
        : "r"(a[0]), "r"(a[1]), "r"(a[2]), "r"(a[3]),
          "r"(b[0]), "r"(b[1]));
}

struct SmemGemm {
    float As[2][BK][BMP];
    float Ws[2][BK][BMP];
};
union SmemPhase1 {
    SmemGemm g;
    int sIdx[Kdim];
};

// ====================================================================
// Kernel 0: fp32 -> fp16 mirror of x. Each thread converts 8 floats.
// ====================================================================
__global__ void __launch_bounds__(256)
convert_half_kernel(const float* __restrict__ x)
{
    const int i = blockIdx.x * 256 + threadIdx.x;     // 8 floats per thread
    const float4 a = ((const float4*)x)[2 * i];
    const float4 b = ((const float4*)x)[2 * i + 1];
    __half2 h[4];
    h[0] = __floats2half2_rn(a.x, a.y);
    h[1] = __floats2half2_rn(a.z, a.w);
    h[2] = __floats2half2_rn(b.x, b.y);
    h[3] = __floats2half2_rn(b.z, b.w);
    ((uint4*)g_xhalf)[i] = *(const uint4*)h;
}

// ====================================================================
// GEMM tile worker (proven R5/R14): 128x128 tile of
//   H[rowBase.., outColBase..] = A[rowBase..,:] @ W[colBase..,:]^T + bias
// 256 threads, 8 warps (4x2) each 32x64, BK=16 double-buffered.
// ====================================================================
__device__ __forceinline__ void gemm_tile(
    const float* __restrict__ A, const float* __restrict__ W,
    const float* __restrict__ bias,
    int rowBase, int colBase, int outColBase,
    float* __restrict__ H, SmemGemm* sm)
{
    const int tid  = threadIdx.x;
    const int lane = tid & 31;
    const int warp = tid >> 5;
    const int wm = (warp & 3) * 32;
    const int wn = (warp >> 2) * 64;
    const int g  = lane >> 2;
    const int t  = lane & 3;

    float acc[2][8][4];
#pragma unroll
    for (int mt = 0; mt < 2; mt++)
#pragma unroll
        for (int nt = 0; nt < 8; nt++)
#pragma unroll
            for (int i = 0; i < 4; i++) acc[mt][nt][i] = 0.f;

    const int srow = tid >> 2;
    const int skq  = tid & 3;

#define STAGE(buf, k0)                                                          \
    {                                                                           \
        _Pragma("unroll")                                                       \
        for (int tt = 0; tt < 2; tt++) {                                        \
            const int row = srow + 64 * tt;                                     \
            float4 va = *(const float4*)(A + (size_t)(rowBase + row) * Fin + (k0) + skq * 4); \
            sm->As[buf][skq * 4 + 0][row] = to_tf32(va.x);                      \
            sm->As[buf][skq * 4 + 1][row] = to_tf32(va.y);                      \
            sm->As[buf][skq * 4 + 2][row] = to_tf32(va.z);                      \
            sm->As[buf][skq * 4 + 3][row] = to_tf32(va.w);                      \
            float4 vw = *(const float4*)(W + (size_t)(colBase + row) * Fin + (k0) + skq * 4); \
            sm->Ws[buf][skq * 4 + 0][row] = to_tf32(vw.x);                      \
            sm->Ws[buf][skq * 4 + 1][row] = to_tf32(vw.y);                      \
            sm->Ws[buf][skq * 4 + 2][row] = to_tf32(vw.z);                      \
            sm->Ws[buf][skq * 4 + 3][row] = to_tf32(vw.w);                      \
        }                                                                       \
    }

    STAGE(0, 0);
    __syncthreads();

    const int NSTAGE = Fin / BK;  // 16
    for (int s = 0; s < NSTAGE; s++) {
        if (s + 1 < NSTAGE) STAGE((s + 1) & 1, (s + 1) * BK);
        const int buf = s & 1;

#pragma unroll
        for (int ks = 0; ks < 2; ks++) {
            const int k8 = ks * 8;
            uint32_t a[2][4];
#pragma unroll
            for (int mt = 0; mt < 2; mt++) {
                const int m0 = wm + mt * 16 + g;
                a[mt][0] = __float_as_uint(sm->As[buf][k8 + t][m0]);
                a[mt][1] = __float_as_uint(sm->As[buf][k8 + t][m0 + 8]);
                a[mt][2] = __float_as_uint(sm->As[buf][k8 + t + 4][m0]);
                a[mt][3] = __float_as_uint(sm->As[buf][k8 + t + 4][m0 + 8]);
            }
            uint32_t b[8][2];
#pragma unroll
            for (int nt = 0; nt < 8; nt++) {
                const int n0 = wn + nt * 8 + g;
                b[nt][0] = __float_as_uint(sm->Ws[buf][k8 + t][n0]);
                b[nt][1] = __float_as_uint(sm->Ws[buf][k8 + t + 4][n0]);
            }
#pragma unroll
            for (int mt = 0; mt < 2; mt++)
#pragma unroll
                for (int nt = 0; nt < 8; nt++)
                    mma_tf32(acc[mt][nt], a[mt], b[nt]);
        }
        __syncthreads();
    }
#undef STAGE

#pragma unroll
    for (int nt = 0; nt < 8; nt++) {
        const int c = wn + nt * 8 + t * 2;
        const float b0 = bias[colBase + c];
        const float b1 = bias[colBase + c + 1];
#pragma unroll
        for (int mt = 0; mt < 2; mt++) {
            const int r0 = rowBase + wm + mt * 16 + g;
            float2 v0 = make_float2(acc[mt][nt][0] + b0, acc[mt][nt][1] + b1);
            float2 v1 = make_float2(acc[mt][nt][2] + b0, acc[mt][nt][3] + b1);
            *(float2*)(H + (size_t)r0 * C2 + outColBase + c)       = v0;
            *(float2*)(H + (size_t)(r0 + 8) * C2 + outColBase + c) = v1;
        }
    }
}

// ====================================================================
// Phase 1 (R14-proven ordering): block-specialized launch.
//   blocks [0, 256):    self GEMM   H[:, 0:256] = X @ Wx^T + Wx_b
//   blocks [256, 2304): neighbor gather-mean (fp16 reads) -> g_xneib
// ====================================================================
__global__ void __launch_bounds__(256, 2)
phase1_kernel(const float* __restrict__ x, const int* __restrict__ idx,
              const float* __restrict__ Wx, const float* __restrict__ Wxb,
              float* __restrict__ H)
{
    __shared__ SmemPhase1 sh;

    if (blockIdx.x < 256) {
        const int rowBase = (blockIdx.x >> 1) * BM;
        const int colBase = (blockIdx.x & 1) * BN;
        gemm_tile(x, Wx, Wxb, rowBase, colBase, colBase, H, &sh.g);
        return;
    }

    // ---- gather: one block per n; warp b owns batch b; lane owns one uint4
    const int n = blockIdx.x - 256;               // 0..2047
    if (threadIdx.x < Kdim) sh.sIdx[threadIdx.x] = idx[n * Kdim + threadIdx.x];
    __syncthreads();

    const int b    = threadIdx.x >> 5;            // batch 0..7
    const int lane = threadIdx.x & 31;            // uint4 lane in 512B fp16 row
    const uint4* __restrict__ Xh = (const uint4*)g_xhalf;   // row = 32 uint4
    const float s = 1.0f / (float)Kdim;

    float acc[8];
#pragma unroll
    for (int i = 0; i < 8; i++) acc[i] = 0.f;

#pragma unroll
    for (int k = 0; k < Kdim; k++) {
        const int j = sh.sIdx[k];
        uint4 v = Xh[(size_t)(((b << 11) + j) << 5) + lane];
        const __half2* h = (const __half2*)&v;
#pragma unroll
        for (int p = 0; p < 4; p++) {
            float2 f = __half22float2(h[p]);
            acc[2 * p]     += f.x;
            acc[2 * p + 1] += f.y;
        }
    }
    float4 o0 = make_float4(acc[0] * s, acc[1] * s, acc[2] * s, acc[3] * s);
    float4 o1 = make_float4(acc[4] * s, acc[5] * s, acc[6] * s, acc[7] * s);
    float* dst = g_xneib + (size_t)(((b << 11) + n) << 8) + lane * 8;
    *(float4*)(dst)     = o0;
    *(float4*)(dst + 4) = o1;
}

// ====================================================================
// Phase 2: neighbor GEMM  H[:, 256:512] = xneib @ Wn^T + Wn_b
// ====================================================================
__global__ void __launch_bounds__(256, 2)
gemm_neib_kernel(const float* __restrict__ Wn, const float* __restrict__ Wnb,
                 float* __restrict__ H)
{
    __shared__ SmemGemm sh;
    const int rowBase = blockIdx.x * BM;
    const int colBase = blockIdx.y * BN;
    gemm_tile(g_xneib, Wn, Wnb, rowBase, colBase, 256 + colBase, H, &sh);
}

// ====================================================================
// Kernel 3: READ-ONLY stats. Per row: inv-norm -> g_inv; per-channel
// partial (sum, sumsq) of relu(h*inv). H is NOT rewritten (apply
// recomputes the normalization from raw H + g_inv).
// Grid: STAT_BLOCKS x 256 (4 blocks/SM -> occupancy fix for the
// measured 18.4us / occ=12% latency bottleneck).
// ====================================================================
__global__ void __launch_bounds__(256)
norm_relu_stats_kernel(const float* __restrict__ H)
{
    const int wid    = threadIdx.x >> 5;
    const int lane   = threadIdx.x & 31;
    const int gwarp  = blockIdx.x * 8 + wid;
    const int nwarps = STAT_BLOCKS * 8;

    float s[16], q[16];
#pragma unroll
    for (int i = 0; i < 16; i++) { s[i] = 0.f; q[i] = 0.f; }

    for (int r = gwarp; r < MROWS; r += nwarps) {
        const float4* __restrict__ Hr = (const float4*)(H + (size_t)r * C2);
        float4 v[4];
#pragma unroll
        for (int j = 0; j < 4; j++) v[j] = Hr[j * 32 + lane];

        float ss = 0.f;
#pragma unroll
        for (int j = 0; j < 4; j++)
            ss += v[j].x * v[j].x + v[j].y * v[j].y + v[j].z * v[j].z + v[j].w * v[j].w;
#pragma unroll
        for (int o = 16; o > 0; o >>= 1)
            ss += __shfl_xor_sync(0xffffffffu, ss, o);

        const float inv = 1.0f / fmaxf(sqrtf(ss), 1e-12f);
        if (lane == 0) g_inv[r] = inv;

#pragma unroll
        for (int j = 0; j < 4; j++) {
            float4 u;
            u.x = fmaxf(v[j].x * inv, 0.f);
            u.y = fmaxf(v[j].y * inv, 0.f);
            u.z = fmaxf(v[j].z * inv, 0.f);
            u.w = fmaxf(v[j].w * inv, 0.f);
            s[j * 4 + 0] += u.x;  q[j * 4 + 0] += u.x * u.x;
            s[j * 4 + 1] += u.y;  q[j * 4 + 1] += u.y * u.y;
            s[j * 4 + 2] += u.z;  q[j * 4 + 2] += u.z * u.z;
            s[j * 4 + 3] += u.w;  q[j * 4 + 3] += u.w * u.w;
        }
    }

    __shared__ float smS[8][C2];
    __shared__ float smQ[8][C2];
#pragma unroll
    for (int j = 0; j < 4; j++)
#pragma unroll
        for (int i = 0; i < 4; i++) {
            const int c = j * 128 + lane * 4 + i;
            smS[wid][c] = s[j * 4 + i];
            smQ[wid][c] = q[j * 4 + i];
        }
    __syncthreads();

    for (int c = threadIdx.x; c < C2; c += blockDim.x) {
        float S = 0.f, Q = 0.f;
#pragma unroll
        for (int w = 0; w < 8; w++) { S += smS[w][c]; Q += smQ[w][c]; }
        g_partS[c * STAT_BLOCKS + blockIdx.x] = S;
        g_partQ[c * STAT_BLOCKS + blockIdx.x] = Q;
    }
}

// ====================================================================
// Kernel 4: finalize BN stats. 64 blocks x 8 warps = one warp per channel;
// coalesced float4 reads over STAT_BLOCKS partials.
// ====================================================================
__global__ void __launch_bounds__(256)
bn_finalize_kernel(const float* __restrict__ gamma, const float* __restrict__ beta)
{
    const int c    = blockIdx.x * 8 + (threadIdx.x >> 5);   // 0..511
    const int lane = threadIdx.x & 31;
    float S = 0.f, Q = 0.f;
    for (int i = lane * 4; i < STAT_BLOCKS; i += 128) {
        float4 s4 = *(const float4*)&g_partS[c * STAT_BLOCKS + i];
        float4 q4 = *(const float4*)&g_partQ[c * STAT_BLOCKS + i];
        S += s4.x + s4.y + s4.z + s4.w;
        Q += q4.x + q4.y + q4.z + q4.w;
    }
#pragma unroll
    for (int o = 16; o > 0; o >>= 1) {
        S += __shfl_xor_sync(0xffffffffu, S, o);
        Q += __shfl_xor_sync(0xffffffffu, Q, o);
    }
    if (lane == 0) {
        const float invN = 1.0f / (float)MROWS;
        const float mean = S * invN;
        const float var  = Q * invN - mean * mean;
        const float sc   = gamma[c] * rsqrtf(var + 1e-5f);
        g_scale[c] = sc;
        g_shift[c] = beta[c] - mean * sc;
    }
}

// ====================================================================
// Kernel 5: apply in place: y = relu(h*inv[row]) * scale[c] + shift[c]
// (recomputes the normalization the stats kernel measured — identical
// arithmetic, so results match the old two-pass scheme bit-for-bit)
// ====================================================================
__global__ void __launch_bounds__(256)
bn_apply_kernel(float* __restrict__ H)
{
    __shared__ float4 ssc[C2 / 4];
    __shared__ float4 ssh[C2 / 4];
    for (int i = threadIdx.x; i < C2 / 4; i += blockDim.x) {
        ssc[i] = ((const float4*)g_scale)[i];
        ssh[i] = ((const float4*)g_shift)[i];
    }
    __syncthreads();

    const int total = MROWS * C2 / 4;
    float4* __restrict__ H4 = (float4*)H;
    for (int idx = blockIdx.x * blockDim.x + threadIdx.x; idx < total;
         idx += gridDim.x * blockDim.x) {
        const int c4  = idx & (C2 / 4 - 1);
        const int row = idx >> 7;                 // 128 float4 per row
        const float inv = g_inv[row];
        float4 v = H4[idx];
        const float4 sc = ssc[c4];
        const float4 sh = ssh[c4];
        v.x = fmaxf(v.x * inv, 0.f) * sc.x + sh.x;
        v.y = fmaxf(v.y * inv, 0.f) * sc.y + sh.y;
        v.z = fmaxf(v.z * inv, 0.f) * sc.z + sh.z;
        v.w = fmaxf(v.w * inv, 0.f) * sc.w + sh.w;
        H4[idx] = v;
    }
}

// ====================================================================
// Launch
// ====================================================================
extern "C" void kernel_launch(void* const* d_in, const int* in_sizes, int n_in,
                              void* d_out, int out_size)
{
    const float* x     = (const float*)d_in[0];
    const int*   idx   = (const int*)  d_in[1];
    const float* Wxw   = (const float*)d_in[2];
    const float* Wxb   = (const float*)d_in[3];
    const float* Wnw   = (const float*)d_in[4];
    const float* Wnb   = (const float*)d_in[5];
    const float* gamma = (const float*)d_in[6];
    const float* beta  = (const float*)d_in[7];
    float* H = (float*)d_out;

    // fp16 mirror of x (feeds the gather only; GEMM numerics unchanged)
    convert_half_kernel<<<MROWS * Fin / 8 / 256, 256>>>(x);

    // Phase 1: self GEMM (256 tiles) + fp16 neighbor gather (2048 blocks)
    phase1_kernel<<<256 + Ndim, 256>>>(x, idx, Wxw, Wxb, H);

    // Phase 2: neighbor GEMM
    dim3 ngrid(MROWS / BM, 2);
    gemm_neib_kernel<<<ngrid, 256>>>(Wnw, Wnb, H);

    norm_relu_stats_kernel<<<STAT_BLOCKS, 256>>>(H);
    bn_finalize_kernel<<<64, 256>>>(gamma, beta);
    bn_apply_kernel<<<4096, 256>>>(H);
}